// round 2
// baseline (speedup 1.0000x reference)
#include <cuda_runtime.h>
#include <cstdint>

typedef unsigned long long ull;

#define N_MAX 50000
#define E_MAX 800000
#define B_MAX 1024

// ---------------- device scratch ----------------
__device__ int      g_deg   [N_MAX];
__device__ int      g_rowptr[N_MAX + 1];
__device__ int      g_woff  [N_MAX];
__device__ int      g_eid   [E_MAX];
__device__ float    g_nr    [(size_t)N_MAX * 72];
__device__ float    g_ya    [(size_t)N_MAX * 64];
__device__ float    g_yb    [(size_t)N_MAX * 64];
__device__ float    g_ea1   [(size_t)E_MAX * 64];
__device__ float    g_ea2   [(size_t)E_MAX * 64];
__device__ int      g_gcnt  [B_MAX];
__device__ int      g_head  [B_MAX];
__device__ unsigned g_pool  [B_MAX * 64];

// ---------------- zero ----------------
__global__ void k_zero(int N, int B) {
    int total = N + B + B * 64;
    for (int i = blockIdx.x * 256 + threadIdx.x; i < total; i += gridDim.x * 256) {
        if (i < N)              g_deg[i] = 0;
        else if (i < N + B)     g_gcnt[i - N] = 0;
        else                    g_pool[i - N - B] = 0u;
    }
}

// ---------------- degree count + per-graph node count ----------------
__global__ void k_count(const int* __restrict__ col, const int* __restrict__ batch,
                        int E, int N) {
    int i = blockIdx.x * 256 + threadIdx.x;
    if (i < E) atomicAdd(&g_deg[col[i]], 1);
    if (i < N) atomicAdd(&g_gcnt[batch[i]], 1);
}

// ---------------- single-block scans: rowptr over deg, head over gcnt ----------------
__global__ void k_scan(int N, int B, int E) {
    __shared__ int s[1024];
    int t = threadIdx.x;
    int C = (N + 1023) / 1024;
    // phase 1: chunk sums
    int sum = 0;
    for (int i = 0; i < C; i++) {
        int idx = t * C + i;
        if (idx < N) sum += g_deg[idx];
    }
    s[t] = sum;
    __syncthreads();
    for (int off = 1; off < 1024; off <<= 1) {
        int add = (t >= off) ? s[t - off] : 0;
        __syncthreads();
        s[t] += add;
        __syncthreads();
    }
    int run = s[t] - sum;   // exclusive prefix
    for (int i = 0; i < C; i++) {
        int idx = t * C + i;
        if (idx < N) {
            g_rowptr[idx] = run;
            g_woff[idx]   = run;
            run += g_deg[idx];
        }
    }
    if (t == 1023) g_rowptr[N] = run;
    __syncthreads();
    // graph head scan (B <= 1024)
    int v = (t < B) ? g_gcnt[t] : 0;
    s[t] = v;
    __syncthreads();
    for (int off = 1; off < 1024; off <<= 1) {
        int add = (t >= off) ? s[t - off] : 0;
        __syncthreads();
        s[t] += add;
        __syncthreads();
    }
    if (t < B) g_head[t] = s[t] - v;
}

// ---------------- CSR fill ----------------
__global__ void k_fill(const int* __restrict__ col, int E) {
    int e = blockIdx.x * 256 + threadIdx.x;
    if (e < E) {
        int pos = atomicAdd(&g_woff[col[e]], 1);
        g_eid[pos] = e;
    }
}

// ---------------- gather aggregation: warp per node ----------------
// MODE 0: src = emb[rel[eid]], write normalized nr (+x0 dims)
// MODE 1: src = ea[eid],       write normalized nr (+x0 dims)
// MODE 2: src = ea[eid],       write node_rep to out + pooled atomicMax
template <int MODE>
__global__ void k_gather(const float* __restrict__ ea, const int* __restrict__ rel,
                         const float* __restrict__ emb, const float* __restrict__ mask,
                         const float* __restrict__ x, const int* __restrict__ batch,
                         float* __restrict__ out_node, int N) {
    int warp = (blockIdx.x * 256 + threadIdx.x) >> 5;
    int lane = threadIdx.x & 31;
    if (warp >= N) return;
    int n = warp;
    int s0 = g_rowptr[n], s1 = g_rowptr[n + 1];

    float acc0 = 0.f, acc1 = 0.f, msum = 0.f;
    for (int base = s0; base < s1; base += 32) {
        int cnt = min(s1 - base, 32);
        int eid = 0; float m = 0.f; int rl = 0;
        if (lane < cnt) {
            eid = g_eid[base + lane];
            m = __ldg(&mask[eid]);
            if (MODE == 0) rl = __ldg(&rel[eid]);
        }
        msum += m;
#pragma unroll 4
        for (int j = 0; j < cnt; j++) {
            float mm = __shfl_sync(0xffffffffu, m, j);
            const float* src;
            if (MODE == 0) {
                int r = __shfl_sync(0xffffffffu, rl, j);
                src = &emb[(size_t)r * 64];
            } else {
                int e = __shfl_sync(0xffffffffu, eid, j);
                src = &ea[(size_t)e * 64];
            }
            acc0 += mm * __ldg(&src[lane]);
            acc1 += mm * __ldg(&src[lane + 32]);
        }
    }
    // warp-reduce msum (all lanes end with total)
#pragma unroll
    for (int o = 16; o > 0; o >>= 1) msum += __shfl_xor_sync(0xffffffffu, msum, o);
    float inv = 1.0f / (msum + 1.0f);
    float v0 = acc0 * inv, v1 = acc1 * inv;

    if (MODE == 2) {
        out_node[(size_t)n * 64 + lane]      = v0;
        out_node[(size_t)n * 64 + lane + 32] = v1;
        int b = batch[n];
        unsigned k0 = __float_as_uint(v0);
        k0 = (k0 & 0x80000000u) ? ~k0 : (k0 | 0x80000000u);
        unsigned k1 = __float_as_uint(v1);
        k1 = (k1 & 0x80000000u) ? ~k1 : (k1 | 0x80000000u);
        atomicMax(&g_pool[(size_t)b * 64 + lane], k0);
        atomicMax(&g_pool[(size_t)b * 64 + lane + 32], k1);
    } else {
        float* nr = &g_nr[(size_t)n * 72];
        nr[lane]      = v0;
        nr[lane + 32] = v1;
        if (lane < 8) {
            int b = batch[n];
            int h = g_head[b];
            bool sp = (n == h) || (n == h + 1);
            float xv = (lane < 6 && sp) ? x[(size_t)n * 6 + lane] : 0.f;
            nr[64 + lane] = xv;
        }
    }
}

// ---------------- per-node GEMM: ya = W[:,:70]@nr + b, yb = W[:,70:140]@nr ----------------
#define NPB 8
__global__ void k_node(const float* __restrict__ W, const float* __restrict__ b, int N) {
    __shared__ float sW[128 * 70];
    __shared__ float snrx[NPB][72];
    int t = threadIdx.x;
    int nb = blockIdx.x * NPB;
    for (int i = t; i < 128 * 70; i += 256) {
        int r = i / 70, k = i % 70;
        sW[i] = (r < 64) ? W[r * 204 + k] : W[(r - 64) * 204 + 70 + k];
    }
    for (int i = t; i < NPB * 18; i += 256) {
        int ln = i / 18, q = i % 18;
        int n = nb + ln;
        float4 v = make_float4(0.f, 0.f, 0.f, 0.f);
        if (n < N) v = *(const float4*)(&g_nr[(size_t)n * 72 + q * 4]);
        *(float4*)(&snrx[ln][q * 4]) = v;
    }
    __syncthreads();
    int o = t & 127;
    int half = t >> 7;
    float acc[4] = {0.f, 0.f, 0.f, 0.f};
    const float* wrow = &sW[o * 70];
#pragma unroll 2
    for (int k = 0; k < 70; k++) {
        float w = wrow[k];
        acc[0] += w * snrx[half * 4 + 0][k];
        acc[1] += w * snrx[half * 4 + 1][k];
        acc[2] += w * snrx[half * 4 + 2][k];
        acc[3] += w * snrx[half * 4 + 3][k];
    }
    float bias = (o < 64) ? b[o] : 0.f;
#pragma unroll
    for (int j = 0; j < 4; j++) {
        int n = nb + half * 4 + j;
        if (n < N) {
            if (o < 64) g_ya[(size_t)n * 64 + o]        = acc[j] + bias;
            else        g_yb[(size_t)n * 64 + (o - 64)] = acc[j];
        }
    }
}

// ---------------- per-edge GEMM with packed f32x2 FMA ----------------
#define EPB 128
#define SA_STRIDE 132
#define SWD_STRIDE 66
#define EDGE_SMEM (64 * SWD_STRIDE * 8 + 64 * SA_STRIDE * 4)

__device__ __forceinline__ void fma_x2(ull& d, ull a, ull b) {
    asm("fma.rn.f32x2 %0, %1, %2, %0;" : "+l"(d) : "l"(a), "l"(b));
}
__device__ __forceinline__ float unpack_lo(ull v) { return __uint_as_float((unsigned)v); }
__device__ __forceinline__ float unpack_hi(ull v) { return __uint_as_float((unsigned)(v >> 32)); }

template <bool USE_EMB>
__global__ void k_edge(const float* __restrict__ ea_in, const float* __restrict__ W,
                       const int* __restrict__ row, const int* __restrict__ col,
                       const int* __restrict__ rel, const float* __restrict__ emb,
                       float* __restrict__ ea_out, int E) {
    extern __shared__ char smraw[];
    ull*   sWd = (ull*)smraw;                              // [64][SWD_STRIDE] duplicated pairs
    float* sA  = (float*)(smraw + 64 * SWD_STRIDE * 8);    // [64][SA_STRIDE] k-major edges
    int t = threadIdx.x;
    long eb = (long)blockIdx.x * EPB;

    // W_c transposed + duplicated: sWd[k][o] = {w,w}
    for (int i = t; i < 64 * 64; i += 256) {
        int o = i & 63, k = i >> 6;
        unsigned u = __float_as_uint(W[o * 204 + 140 + k]);
        sWd[k * SWD_STRIDE + o] = ((ull)u << 32) | u;
    }
    // ea tile transposed
    for (int i = t; i < EPB * 16; i += 256) {
        int le = i >> 4, k4 = i & 15;
        long e = eb + le;
        float4 v = make_float4(0.f, 0.f, 0.f, 0.f);
        if (e < E) {
            if (USE_EMB) v = *(const float4*)(&emb[(size_t)__ldg(&rel[e]) * 64 + k4 * 4]);
            else         v = *(const float4*)(&ea_in[(size_t)e * 64 + k4 * 4]);
        }
        sA[(k4 * 4 + 0) * SA_STRIDE + le] = v.x;
        sA[(k4 * 4 + 1) * SA_STRIDE + le] = v.y;
        sA[(k4 * 4 + 2) * SA_STRIDE + le] = v.z;
        sA[(k4 * 4 + 3) * SA_STRIDE + le] = v.w;
    }
    __syncthreads();

    int te = t & 15;   // edges te*8 .. te*8+7 (4 packed pairs)
    int to = t >> 4;   // outs  to*4 .. to*4+3
    ull acc[4][4];
#pragma unroll
    for (int p = 0; p < 4; p++)
#pragma unroll
        for (int j = 0; j < 4; j++) acc[p][j] = 0ull;

#pragma unroll 2
    for (int k = 0; k < 64; k++) {
        const ulonglong2* ap = (const ulonglong2*)(&sA[k * SA_STRIDE + te * 8]);
        ulonglong2 a01 = ap[0], a23 = ap[1];
        const ulonglong2* wp = (const ulonglong2*)(&sWd[k * SWD_STRIDE + to * 4]);
        ulonglong2 w01 = wp[0], w23 = wp[1];
        ull av[4] = {a01.x, a01.y, a23.x, a23.y};
        ull wv[4] = {w01.x, w01.y, w23.x, w23.y};
#pragma unroll
        for (int p = 0; p < 4; p++)
#pragma unroll
            for (int j = 0; j < 4; j++) fma_x2(acc[p][j], av[p], wv[j]);
    }

#pragma unroll
    for (int p = 0; p < 4; p++) {
#pragma unroll
        for (int h = 0; h < 2; h++) {
            long e = eb + te * 8 + 2 * p + h;
            if (e < E) {
                int r = __ldg(&row[e]);
                int c = __ldg(&col[e]);
                float4 u = *(const float4*)(&g_ya[(size_t)r * 64 + to * 4]);
                float4 v = *(const float4*)(&g_yb[(size_t)c * 64 + to * 4]);
                float g0 = h ? unpack_hi(acc[p][0]) : unpack_lo(acc[p][0]);
                float g1 = h ? unpack_hi(acc[p][1]) : unpack_lo(acc[p][1]);
                float g2 = h ? unpack_hi(acc[p][2]) : unpack_lo(acc[p][2]);
                float g3 = h ? unpack_hi(acc[p][3]) : unpack_lo(acc[p][3]);
                float4 o;
                o.x = fmaxf(g0 + u.x + v.x, 0.f);
                o.y = fmaxf(g1 + u.y + v.y, 0.f);
                o.z = fmaxf(g2 + u.z + v.z, 0.f);
                o.w = fmaxf(g3 + u.w + v.w, 0.f);
                *(float4*)(&ea_out[(size_t)e * 64 + to * 4]) = o;
            }
        }
    }
}

// ---------------- graph emb assembly ----------------
__global__ void k_graph(const float* __restrict__ node_rep, float* __restrict__ out_graph, int B) {
    int idx = blockIdx.x * 256 + threadIdx.x;
    if (idx >= B * 192) return;
    int b = idx / 192, j = idx % 192;
    float v;
    if (j < 64) {
        unsigned k = g_pool[(size_t)b * 64 + j];
        k = (k & 0x80000000u) ? (k & 0x7FFFFFFFu) : ~k;
        v = __uint_as_float(k);
    } else if (j < 128) {
        v = node_rep[(size_t)g_head[b] * 64 + (j - 64)];
    } else {
        v = node_rep[((size_t)g_head[b] + 1) * 64 + (j - 128)];
    }
    out_graph[idx] = v;
}

// ---------------- launch ----------------
extern "C" void kernel_launch(void* const* d_in, const int* in_sizes, int n_in,
                              void* d_out, int out_size) {
    const float* x     = (const float*)d_in[0];
    const int*   eidx  = (const int*)  d_in[1];
    const int*   erel  = (const int*)  d_in[2];
    const int*   batch = (const int*)  d_in[3];
    const float* mask  = (const float*)d_in[4];
    const float* emb   = (const float*)d_in[5];
    const float* Wl[3] = {(const float*)d_in[6], (const float*)d_in[8], (const float*)d_in[10]};
    const float* bl[3] = {(const float*)d_in[7], (const float*)d_in[9], (const float*)d_in[11]};

    int N = in_sizes[0] / 6;
    int E = in_sizes[2];
    int B = (int)(((long)out_size - 64L * (N + E)) / 192L);

    const int* row = eidx;
    const int* col = eidx + E;

    float* out       = (float*)d_out;
    float* out_graph = out;
    float* out_node  = out + (size_t)B * 192;
    float* out_ea    = out_node + (size_t)N * 64;

    void *p_ea1, *p_ea2;
    cudaGetSymbolAddress(&p_ea1, g_ea1);
    cudaGetSymbolAddress(&p_ea2, g_ea2);
    float* ea1 = (float*)p_ea1;
    float* ea2 = (float*)p_ea2;

    cudaFuncSetAttribute(k_edge<true>,  cudaFuncAttributeMaxDynamicSharedMemorySize, EDGE_SMEM);
    cudaFuncSetAttribute(k_edge<false>, cudaFuncAttributeMaxDynamicSharedMemorySize, EDGE_SMEM);

    int grid_g = (N * 32 + 255) / 256;   // warp per node
    int grid_n = (N + NPB - 1) / NPB;
    int grid_e = (E + EPB - 1) / EPB;
    int M = (E > N ? E : N);

    // CSR build
    k_zero<<<128, 256>>>(N, B);
    k_count<<<(M + 255) / 256, 256>>>(col, batch, E, N);
    k_scan<<<1, 1024>>>(N, B, E);
    k_fill<<<(E + 255) / 256, 256>>>(col, E);

    // layer 0
    k_gather<0><<<grid_g, 256>>>(nullptr, erel, emb, mask, x, batch, nullptr, N);
    k_node<<<grid_n, 256>>>(Wl[0], bl[0], N);
    k_edge<true><<<grid_e, 256, EDGE_SMEM>>>(nullptr, Wl[0], row, col, erel, emb, ea1, E);
    // layer 1
    k_gather<1><<<grid_g, 256>>>(ea1, nullptr, nullptr, mask, x, batch, nullptr, N);
    k_node<<<grid_n, 256>>>(Wl[1], bl[1], N);
    k_edge<false><<<grid_e, 256, EDGE_SMEM>>>(ea1, Wl[1], row, col, nullptr, nullptr, ea2, E);
    // layer 2 (final ea straight to d_out)
    k_gather<1><<<grid_g, 256>>>(ea2, nullptr, nullptr, mask, x, batch, nullptr, N);
    k_node<<<grid_n, 256>>>(Wl[2], bl[2], N);
    k_edge<false><<<grid_e, 256, EDGE_SMEM>>>(ea2, Wl[2], row, col, nullptr, nullptr, out_ea, E);
    // final aggregation + pooling + graph emb
    k_gather<2><<<grid_g, 256>>>(out_ea, nullptr, nullptr, mask, x, batch, out_node, N);
    k_graph<<<(B * 192 + 255) / 256, 256>>>(out_node, out_graph, B);
}

// round 3
// speedup vs baseline: 1.0355x; 1.0355x over previous
#include <cuda_runtime.h>
#include <cstdint>

typedef unsigned long long ull;

#define N_MAX 50000
#define E_MAX 800000
#define B_MAX 1024

// ---------------- device scratch ----------------
__device__ int      g_deg   [N_MAX];
__device__ int      g_rowptr[N_MAX + 1];
__device__ int      g_woff  [N_MAX];
__device__ int      g_peid  [E_MAX];   // CSR position -> original edge id
__device__ int      g_prow  [E_MAX];   // CSR position -> row (source node)
__device__ int      g_pcol  [E_MAX];   // CSR position -> col (dest node, sorted)
__device__ int      g_prel  [E_MAX];   // CSR position -> relation
__device__ float    g_pmask [E_MAX];   // CSR position -> mask
__device__ float    g_nr    [(size_t)N_MAX * 72];
__device__ float    g_ya    [(size_t)N_MAX * 64];
__device__ float    g_yb    [(size_t)N_MAX * 64];
__device__ float    g_ea1   [(size_t)E_MAX * 64];
__device__ float    g_ea2   [(size_t)E_MAX * 64];
__device__ int      g_gcnt  [B_MAX];
__device__ int      g_head  [B_MAX];
__device__ unsigned g_pool  [B_MAX * 64];

// ---------------- zero ----------------
__global__ void k_zero(int N, int B) {
    int total = N + B + B * 64;
    for (int i = blockIdx.x * 256 + threadIdx.x; i < total; i += gridDim.x * 256) {
        if (i < N)          g_deg[i] = 0;
        else if (i < N + B) g_gcnt[i - N] = 0;
        else                g_pool[i - N - B] = 0u;
    }
}

// ---------------- degree count + per-graph node count ----------------
__global__ void k_count(const int* __restrict__ col, const int* __restrict__ batch,
                        int E, int N) {
    int i = blockIdx.x * 256 + threadIdx.x;
    if (i < E) atomicAdd(&g_deg[col[i]], 1);
    if (i < N) atomicAdd(&g_gcnt[batch[i]], 1);
}

// ---------------- single-block scans ----------------
__global__ void k_scan(int N, int B) {
    __shared__ int s[1024];
    int t = threadIdx.x;
    int C = (N + 1023) / 1024;
    int sum = 0;
    for (int i = 0; i < C; i++) {
        int idx = t * C + i;
        if (idx < N) sum += g_deg[idx];
    }
    s[t] = sum;
    __syncthreads();
    for (int off = 1; off < 1024; off <<= 1) {
        int add = (t >= off) ? s[t - off] : 0;
        __syncthreads();
        s[t] += add;
        __syncthreads();
    }
    int run = s[t] - sum;
    for (int i = 0; i < C; i++) {
        int idx = t * C + i;
        if (idx < N) {
            g_rowptr[idx] = run;
            g_woff[idx]   = run;
            run += g_deg[idx];
        }
    }
    if (t == 1023) g_rowptr[N] = run;
    __syncthreads();
    int v = (t < B) ? g_gcnt[t] : 0;
    s[t] = v;
    __syncthreads();
    for (int off = 1; off < 1024; off <<= 1) {
        int add = (t >= off) ? s[t - off] : 0;
        __syncthreads();
        s[t] += add;
        __syncthreads();
    }
    if (t < B) g_head[t] = s[t] - v;
}

// ---------------- CSR fill: build permuted edge metadata ----------------
__global__ void k_fill(const int* __restrict__ row, const int* __restrict__ col,
                       const int* __restrict__ rel, const float* __restrict__ mask, int E) {
    int e = blockIdx.x * 256 + threadIdx.x;
    if (e < E) {
        int c = col[e];
        int pos = atomicAdd(&g_woff[c], 1);
        g_peid [pos] = e;
        g_prow [pos] = row[e];
        g_pcol [pos] = c;
        g_prel [pos] = rel[e];
        g_pmask[pos] = mask[e];
    }
}

// ---------------- gather aggregation: warp per node, streaming ----------------
// MODE 0: src = emb[prel[p]]           -> nr (+x0)
// MODE 1: src = ea[p] (permuted, seq)  -> nr (+x0)
// MODE 2: src = ea[peid[p]] (orig ord) -> node_rep out + pooled max
template <int MODE>
__global__ void k_gather(const float* __restrict__ ea, const float* __restrict__ emb,
                         const float* __restrict__ x, const int* __restrict__ batch,
                         float* __restrict__ out_node, int N) {
    int n = (blockIdx.x * 256 + threadIdx.x) >> 5;
    int lane = threadIdx.x & 31;
    if (n >= N) return;
    int s0 = g_rowptr[n], s1 = g_rowptr[n + 1];

    float acc0 = 0.f, acc1 = 0.f, msum = 0.f;
    for (int p = s0; p < s1; p++) {
        float mm = __ldg(&g_pmask[p]);
        msum += mm;
        const float* src;
        if (MODE == 0)      src = &emb[(size_t)__ldg(&g_prel[p]) * 64];
        else if (MODE == 2) src = &ea[(size_t)__ldg(&g_peid[p]) * 64];
        else                src = &ea[(size_t)p * 64];
        acc0 += mm * __ldg(&src[lane]);
        acc1 += mm * __ldg(&src[lane + 32]);
    }
    float inv = 1.0f / (msum + 1.0f);   // identical on all lanes
    float v0 = acc0 * inv, v1 = acc1 * inv;

    if (MODE == 2) {
        out_node[(size_t)n * 64 + lane]      = v0;
        out_node[(size_t)n * 64 + lane + 32] = v1;
        int b = batch[n];
        unsigned k0 = __float_as_uint(v0);
        k0 = (k0 & 0x80000000u) ? ~k0 : (k0 | 0x80000000u);
        unsigned k1 = __float_as_uint(v1);
        k1 = (k1 & 0x80000000u) ? ~k1 : (k1 | 0x80000000u);
        atomicMax(&g_pool[(size_t)b * 64 + lane], k0);
        atomicMax(&g_pool[(size_t)b * 64 + lane + 32], k1);
    } else {
        float* nr = &g_nr[(size_t)n * 72];
        nr[lane]      = v0;
        nr[lane + 32] = v1;
        if (lane < 8) {
            int b = batch[n];
            int h = g_head[b];
            bool sp = (n == h) || (n == h + 1);
            float xv = (lane < 6 && sp) ? x[(size_t)n * 6 + lane] : 0.f;
            nr[64 + lane] = xv;
        }
    }
}

// ---------------- per-node GEMM: ya = W[:,:70]@nr + b, yb = W[:,70:140]@nr ----------------
#define NPB 8
__global__ void k_node(const float* __restrict__ W, const float* __restrict__ b, int N) {
    __shared__ float sW[128 * 70];
    __shared__ float snrx[NPB][72];
    int t = threadIdx.x;
    int nb = blockIdx.x * NPB;
    for (int i = t; i < 128 * 70; i += 256) {
        int r = i / 70, k = i % 70;
        sW[i] = (r < 64) ? W[r * 204 + k] : W[(r - 64) * 204 + 70 + k];
    }
    for (int i = t; i < NPB * 18; i += 256) {
        int ln = i / 18, q = i % 18;
        int n = nb + ln;
        float4 v = make_float4(0.f, 0.f, 0.f, 0.f);
        if (n < N) v = *(const float4*)(&g_nr[(size_t)n * 72 + q * 4]);
        *(float4*)(&snrx[ln][q * 4]) = v;
    }
    __syncthreads();
    int o = t & 127;
    int half = t >> 7;
    float acc[4] = {0.f, 0.f, 0.f, 0.f};
    const float* wrow = &sW[o * 70];
#pragma unroll 2
    for (int k = 0; k < 70; k++) {
        float w = wrow[k];
        acc[0] += w * snrx[half * 4 + 0][k];
        acc[1] += w * snrx[half * 4 + 1][k];
        acc[2] += w * snrx[half * 4 + 2][k];
        acc[3] += w * snrx[half * 4 + 3][k];
    }
    float bias = (o < 64) ? b[o] : 0.f;
#pragma unroll
    for (int j = 0; j < 4; j++) {
        int n = nb + half * 4 + j;
        if (n < N) {
            if (o < 64) g_ya[(size_t)n * 64 + o]        = acc[j] + bias;
            else        g_yb[(size_t)n * 64 + (o - 64)] = acc[j];
        }
    }
}

// ---------------- per-edge GEMM (CSR position order) ----------------
#define EPB 128
#define SA_STRIDE 132
#define SWD_STRIDE 66
#define EDGE_SMEM (64 * SWD_STRIDE * 8 + 64 * SA_STRIDE * 4)

__device__ __forceinline__ void fma_x2(ull& d, ull a, ull b) {
    asm("fma.rn.f32x2 %0, %1, %2, %0;" : "+l"(d) : "l"(a), "l"(b));
}
__device__ __forceinline__ float unpack_lo(ull v) { return __uint_as_float((unsigned)v); }
__device__ __forceinline__ float unpack_hi(ull v) { return __uint_as_float((unsigned)(v >> 32)); }

// SRC: 0 = emb[prel[p]], 1 = ea_in[p] (sequential)
// DST: 0 = ea_out[p] (sequential), 1 = ea_out[peid[p]] (original order)
template <int SRC, int DST>
__global__ void k_edge(const float* __restrict__ ea_in, const float* __restrict__ W,
                       const float* __restrict__ emb, float* __restrict__ ea_out, int E) {
    extern __shared__ char smraw[];
    ull*   sWd = (ull*)smraw;
    float* sA  = (float*)(smraw + 64 * SWD_STRIDE * 8);
    int t = threadIdx.x;
    long eb = (long)blockIdx.x * EPB;

    for (int i = t; i < 64 * 64; i += 256) {
        int o = i & 63, k = i >> 6;
        unsigned u = __float_as_uint(W[o * 204 + 140 + k]);
        sWd[k * SWD_STRIDE + o] = ((ull)u << 32) | u;
    }
    for (int i = t; i < EPB * 16; i += 256) {
        int le = i >> 4, k4 = i & 15;
        long p = eb + le;
        float4 v = make_float4(0.f, 0.f, 0.f, 0.f);
        if (p < E) {
            if (SRC == 0) v = *(const float4*)(&emb[(size_t)__ldg(&g_prel[p]) * 64 + k4 * 4]);
            else          v = *(const float4*)(&ea_in[(size_t)p * 64 + k4 * 4]);
        }
        sA[(k4 * 4 + 0) * SA_STRIDE + le] = v.x;
        sA[(k4 * 4 + 1) * SA_STRIDE + le] = v.y;
        sA[(k4 * 4 + 2) * SA_STRIDE + le] = v.z;
        sA[(k4 * 4 + 3) * SA_STRIDE + le] = v.w;
    }
    __syncthreads();

    int te = t & 15;
    int to = t >> 4;
    ull acc[4][4];
#pragma unroll
    for (int p = 0; p < 4; p++)
#pragma unroll
        for (int j = 0; j < 4; j++) acc[p][j] = 0ull;

#pragma unroll 2
    for (int k = 0; k < 64; k++) {
        const ulonglong2* ap = (const ulonglong2*)(&sA[k * SA_STRIDE + te * 8]);
        ulonglong2 a01 = ap[0], a23 = ap[1];
        const ulonglong2* wp = (const ulonglong2*)(&sWd[k * SWD_STRIDE + to * 4]);
        ulonglong2 w01 = wp[0], w23 = wp[1];
        ull av[4] = {a01.x, a01.y, a23.x, a23.y};
        ull wv[4] = {w01.x, w01.y, w23.x, w23.y};
#pragma unroll
        for (int p = 0; p < 4; p++)
#pragma unroll
            for (int j = 0; j < 4; j++) fma_x2(acc[p][j], av[p], wv[j]);
    }

#pragma unroll
    for (int pp = 0; pp < 4; pp++) {
#pragma unroll
        for (int h = 0; h < 2; h++) {
            long p = eb + te * 8 + 2 * pp + h;
            if (p < E) {
                int r = __ldg(&g_prow[p]);
                int c = __ldg(&g_pcol[p]);   // sorted -> L1/L2 reuse
                float4 u = *(const float4*)(&g_ya[(size_t)r * 64 + to * 4]);
                float4 v = *(const float4*)(&g_yb[(size_t)c * 64 + to * 4]);
                float g0 = h ? unpack_hi(acc[pp][0]) : unpack_lo(acc[pp][0]);
                float g1 = h ? unpack_hi(acc[pp][1]) : unpack_lo(acc[pp][1]);
                float g2 = h ? unpack_hi(acc[pp][2]) : unpack_lo(acc[pp][2]);
                float g3 = h ? unpack_hi(acc[pp][3]) : unpack_lo(acc[pp][3]);
                float4 o;
                o.x = fmaxf(g0 + u.x + v.x, 0.f);
                o.y = fmaxf(g1 + u.y + v.y, 0.f);
                o.z = fmaxf(g2 + u.z + v.z, 0.f);
                o.w = fmaxf(g3 + u.w + v.w, 0.f);
                long dst = (DST == 0) ? p : (long)__ldg(&g_peid[p]);
                *(float4*)(&ea_out[(size_t)dst * 64 + to * 4]) = o;
            }
        }
    }
}

// ---------------- graph emb assembly ----------------
__global__ void k_graph(const float* __restrict__ node_rep, float* __restrict__ out_graph, int B) {
    int idx = blockIdx.x * 256 + threadIdx.x;
    if (idx >= B * 192) return;
    int b = idx / 192, j = idx % 192;
    float v;
    if (j < 64) {
        unsigned k = g_pool[(size_t)b * 64 + j];
        k = (k & 0x80000000u) ? (k & 0x7FFFFFFFu) : ~k;
        v = __uint_as_float(k);
    } else if (j < 128) {
        v = node_rep[(size_t)g_head[b] * 64 + (j - 64)];
    } else {
        v = node_rep[((size_t)g_head[b] + 1) * 64 + (j - 128)];
    }
    out_graph[idx] = v;
}

// ---------------- launch ----------------
extern "C" void kernel_launch(void* const* d_in, const int* in_sizes, int n_in,
                              void* d_out, int out_size) {
    const float* x     = (const float*)d_in[0];
    const int*   eidx  = (const int*)  d_in[1];
    const int*   erel  = (const int*)  d_in[2];
    const int*   batch = (const int*)  d_in[3];
    const float* mask  = (const float*)d_in[4];
    const float* emb   = (const float*)d_in[5];
    const float* Wl[3] = {(const float*)d_in[6], (const float*)d_in[8], (const float*)d_in[10]};
    const float* bl[3] = {(const float*)d_in[7], (const float*)d_in[9], (const float*)d_in[11]};

    int N = in_sizes[0] / 6;
    int E = in_sizes[2];
    int B = (int)(((long)out_size - 64L * (N + E)) / 192L);

    const int* row = eidx;
    const int* col = eidx + E;

    float* out       = (float*)d_out;
    float* out_graph = out;
    float* out_node  = out + (size_t)B * 192;
    float* out_ea    = out_node + (size_t)N * 64;

    void *p_ea1, *p_ea2;
    cudaGetSymbolAddress(&p_ea1, g_ea1);
    cudaGetSymbolAddress(&p_ea2, g_ea2);
    float* ea1 = (float*)p_ea1;
    float* ea2 = (float*)p_ea2;

    cudaFuncSetAttribute(k_edge<0,0>, cudaFuncAttributeMaxDynamicSharedMemorySize, EDGE_SMEM);
    cudaFuncSetAttribute(k_edge<1,0>, cudaFuncAttributeMaxDynamicSharedMemorySize, EDGE_SMEM);
    cudaFuncSetAttribute(k_edge<1,1>, cudaFuncAttributeMaxDynamicSharedMemorySize, EDGE_SMEM);

    int grid_g = (N * 32 + 255) / 256;
    int grid_n = (N + NPB - 1) / NPB;
    int grid_e = (E + EPB - 1) / EPB;
    int M = (E > N ? E : N);

    // CSR build (launches 1-4)
    k_zero<<<128, 256>>>(N, B);
    k_count<<<(M + 255) / 256, 256>>>(col, batch, E, N);
    k_scan<<<1, 1024>>>(N, B);
    k_fill<<<(E + 255) / 256, 256>>>(row, col, erel, mask, E);

    // layer 0 (launches 5-7: gather, node, edge -> ncu -s 5 lands here)
    k_gather<0><<<grid_g, 256>>>(nullptr, emb, x, batch, nullptr, N);
    k_node<<<grid_n, 256>>>(Wl[0], bl[0], N);
    k_edge<0,0><<<grid_e, 256, EDGE_SMEM>>>(nullptr, Wl[0], emb, ea1, E);
    // layer 1
    k_gather<1><<<grid_g, 256>>>(ea1, nullptr, x, batch, nullptr, N);
    k_node<<<grid_n, 256>>>(Wl[1], bl[1], N);
    k_edge<1,0><<<grid_e, 256, EDGE_SMEM>>>(ea1, Wl[1], nullptr, ea2, E);
    // layer 2: write final ea to d_out in ORIGINAL edge order
    k_gather<1><<<grid_g, 256>>>(ea2, nullptr, x, batch, nullptr, N);
    k_node<<<grid_n, 256>>>(Wl[2], bl[2], N);
    k_edge<1,1><<<grid_e, 256, EDGE_SMEM>>>(ea2, Wl[2], nullptr, out_ea, E);
    // final aggregation + pooling + graph emb
    k_gather<2><<<grid_g, 256>>>(out_ea, nullptr, x, batch, out_node, N);
    k_graph<<<(B * 192 + 255) / 256, 256>>>(out_node, out_graph, B);
}

// round 4
// speedup vs baseline: 1.0661x; 1.0296x over previous
#include <cuda_runtime.h>
#include <cstdint>

typedef unsigned long long ull;

#define N_MAX 50000
#define E_MAX 800000
#define B_MAX 1024

// ---------------- device scratch ----------------
__device__ int      g_deg   [N_MAX];
__device__ int      g_rowptr[N_MAX + 1];
__device__ int      g_woff  [N_MAX];
__device__ int      g_peid  [E_MAX];
__device__ int      g_prow  [E_MAX];
__device__ int      g_pcol  [E_MAX];
__device__ int      g_prel  [E_MAX];
__device__ float    g_pmask [E_MAX];
__device__ float    g_cntf  [N_MAX];
__device__ float    g_x0    [N_MAX * 6];          // zero-init; only head/tail rows ever written
__device__ float    g_aggA  [(size_t)N_MAX * 64];
__device__ float    g_aggB  [(size_t)N_MAX * 64];
__device__ float    g_ya    [(size_t)N_MAX * 64];
__device__ float    g_yb    [(size_t)N_MAX * 64];
__device__ float    g_ea1   [(size_t)E_MAX * 64];
__device__ float    g_ea2   [(size_t)E_MAX * 64];
__device__ int      g_gcnt  [B_MAX];
__device__ int      g_head  [B_MAX];
__device__ unsigned g_pool  [B_MAX * 64];

// ---------------- counts: degree, masked cnt, per-graph nodes ----------------
__global__ void k_count(const int* __restrict__ col, const float* __restrict__ mask,
                        const int* __restrict__ batch, int E, int N) {
    int i = blockIdx.x * 256 + threadIdx.x;
    if (i < E) {
        int c = col[i];
        atomicAdd(&g_deg[c], 1);
        atomicAdd(&g_cntf[c], mask[i]);
    }
    if (i < N) atomicAdd(&g_gcnt[batch[i]], 1);
}

// ---------------- single-block scans ----------------
__global__ void k_scan(int N, int B) {
    __shared__ int s[1024];
    int t = threadIdx.x;
    int C = (N + 1023) / 1024;
    int sum = 0;
    for (int i = 0; i < C; i++) {
        int idx = t * C + i;
        if (idx < N) sum += g_deg[idx];
    }
    s[t] = sum;
    __syncthreads();
    for (int off = 1; off < 1024; off <<= 1) {
        int add = (t >= off) ? s[t - off] : 0;
        __syncthreads();
        s[t] += add;
        __syncthreads();
    }
    int run = s[t] - sum;
    for (int i = 0; i < C; i++) {
        int idx = t * C + i;
        if (idx < N) {
            g_rowptr[idx] = run;
            g_woff[idx]   = run;
            run += g_deg[idx];
        }
    }
    if (t == 1023) g_rowptr[N] = run;
    __syncthreads();
    int v = (t < B) ? g_gcnt[t] : 0;
    s[t] = v;
    __syncthreads();
    for (int off = 1; off < 1024; off <<= 1) {
        int add = (t >= off) ? s[t - off] : 0;
        __syncthreads();
        s[t] += add;
        __syncthreads();
    }
    if (t < B) g_head[t] = s[t] - v;
}

// ---------------- x0 for head/tail nodes (others stay zero-init) ----------------
__global__ void k_x0set(const float* __restrict__ x, int B, int N) {
    int idx = blockIdx.x * 256 + threadIdx.x;
    if (idx >= B * 16) return;
    int b = idx >> 4, s = idx & 15;
    int n = (s < 8) ? g_head[b] : (g_head[b] + 1);
    int d = s & 7;
    if (d < 6 && n < N) g_x0[n * 6 + d] = x[n * 6 + d];
}

// ---------------- CSR fill ----------------
__global__ void k_fill(const int* __restrict__ row, const int* __restrict__ col,
                       const int* __restrict__ rel, const float* __restrict__ mask, int E) {
    int e = blockIdx.x * 256 + threadIdx.x;
    if (e < E) {
        int c = col[e];
        int pos = atomicAdd(&g_woff[c], 1);
        g_peid [pos] = e;
        g_prow [pos] = row[e];
        g_pcol [pos] = c;
        g_prel [pos] = rel[e];
        g_pmask[pos] = mask[e];
    }
}

// ---------------- layer-0 aggregation: warp per node over emb table ----------------
__global__ void k_gather0(const float* __restrict__ emb, float* __restrict__ agg, int N) {
    int n = (blockIdx.x * 256 + threadIdx.x) >> 5;
    int lane = threadIdx.x & 31;
    if (n >= N) return;
    int s0 = g_rowptr[n], s1 = g_rowptr[n + 1];
    float acc0 = 0.f, acc1 = 0.f;
    for (int p = s0; p < s1; p++) {
        float mm = __ldg(&g_pmask[p]);
        const float* src = &emb[(size_t)__ldg(&g_prel[p]) * 64];
        acc0 += mm * __ldg(&src[lane]);
        acc1 += mm * __ldg(&src[lane + 32]);
    }
    agg[(size_t)n * 64 + lane]      = acc0;
    agg[(size_t)n * 64 + lane + 32] = acc1;
}

// ---------------- per-node GEMM: ya = W[:,:70]@nr + b, yb = W[:,70:140]@nr ----------------
// nr built inline: agg/(cnt+1) for dims 0..63, x0 for 64..69, 0 for 70..71
#define NPB 8
__global__ void k_node(const float* __restrict__ agg, const float* __restrict__ W,
                       const float* __restrict__ b, int N) {
    __shared__ float sW[128 * 70];
    __shared__ float snrx[NPB][72];
    int t = threadIdx.x;
    int nb = blockIdx.x * NPB;
    for (int i = t; i < 128 * 70; i += 256) {
        int r = i / 70, k = i % 70;
        sW[i] = (r < 64) ? W[r * 204 + k] : W[(r - 64) * 204 + 70 + k];
    }
    for (int i = t; i < NPB * 18; i += 256) {
        int ln = i / 18, q = i % 18;
        int n = nb + ln;
        float4 v = make_float4(0.f, 0.f, 0.f, 0.f);
        if (n < N) {
            if (q < 16) {
                v = *(const float4*)(&agg[(size_t)n * 64 + q * 4]);
                float inv = 1.0f / (g_cntf[n] + 1.0f);
                v.x *= inv; v.y *= inv; v.z *= inv; v.w *= inv;
            } else if (q == 16) {
                const float* x0 = &g_x0[(size_t)n * 6];
                v = make_float4(x0[0], x0[1], x0[2], x0[3]);
            } else {
                const float* x0 = &g_x0[(size_t)n * 6];
                v = make_float4(x0[4], x0[5], 0.f, 0.f);
            }
        }
        *(float4*)(&snrx[ln][q * 4]) = v;
    }
    __syncthreads();
    int o = t & 127;
    int half = t >> 7;
    float acc[4] = {0.f, 0.f, 0.f, 0.f};
    const float* wrow = &sW[o * 70];
#pragma unroll 2
    for (int k = 0; k < 70; k++) {
        float w = wrow[k];
        acc[0] += w * snrx[half * 4 + 0][k];
        acc[1] += w * snrx[half * 4 + 1][k];
        acc[2] += w * snrx[half * 4 + 2][k];
        acc[3] += w * snrx[half * 4 + 3][k];
    }
    float bias = (o < 64) ? b[o] : 0.f;
#pragma unroll
    for (int j = 0; j < 4; j++) {
        int n = nb + half * 4 + j;
        if (n < N) {
            if (o < 64) g_ya[(size_t)n * 64 + o]        = acc[j] + bias;
            else        g_yb[(size_t)n * 64 + (o - 64)] = acc[j];
        }
    }
}

// ---------------- per-edge GEMM + fused masked aggregation ----------------
#define EPB 128
#define SA_STRIDE 132
#define SWD_STRIDE 66
#define EDGE_SMEM (64 * SWD_STRIDE * 8 + 64 * SA_STRIDE * 4)

__device__ __forceinline__ void fma_x2(ull& d, ull a, ull b) {
    asm("fma.rn.f32x2 %0, %1, %2, %0;" : "+l"(d) : "l"(a), "l"(b));
}
__device__ __forceinline__ float unpack_lo(ull v) { return __uint_as_float((unsigned)v); }
__device__ __forceinline__ float unpack_hi(ull v) { return __uint_as_float((unsigned)(v >> 32)); }

// SRC: 0 = emb[prel[p]], 1 = ea_in[p] sequential
// DST: 0 = ea_out[p] sequential, 1 = ea_out[peid[p]] original order
template <int SRC, int DST>
__global__ void k_edge(const float* __restrict__ ea_in, const float* __restrict__ W,
                       const float* __restrict__ emb, float* __restrict__ ea_out,
                       float* __restrict__ agg_out, int E) {
    extern __shared__ char smraw[];
    ull*   sWd = (ull*)smraw;
    float* sA  = (float*)(smraw + 64 * SWD_STRIDE * 8);
    int t = threadIdx.x;
    long eb = (long)blockIdx.x * EPB;

    for (int i = t; i < 64 * 64; i += 256) {
        int o = i & 63, k = i >> 6;
        unsigned u = __float_as_uint(W[o * 204 + 140 + k]);
        sWd[k * SWD_STRIDE + o] = ((ull)u << 32) | u;
    }
    for (int i = t; i < EPB * 16; i += 256) {
        int le = i >> 4, k4 = i & 15;
        long p = eb + le;
        float4 v = make_float4(0.f, 0.f, 0.f, 0.f);
        if (p < E) {
            if (SRC == 0) v = *(const float4*)(&emb[(size_t)__ldg(&g_prel[p]) * 64 + k4 * 4]);
            else          v = *(const float4*)(&ea_in[(size_t)p * 64 + k4 * 4]);
        }
        sA[(k4 * 4 + 0) * SA_STRIDE + le] = v.x;
        sA[(k4 * 4 + 1) * SA_STRIDE + le] = v.y;
        sA[(k4 * 4 + 2) * SA_STRIDE + le] = v.z;
        sA[(k4 * 4 + 3) * SA_STRIDE + le] = v.w;
    }
    __syncthreads();

    int te = t & 15;
    int to = t >> 4;
    ull acc[4][4];
#pragma unroll
    for (int p = 0; p < 4; p++)
#pragma unroll
        for (int j = 0; j < 4; j++) acc[p][j] = 0ull;

#pragma unroll 2
    for (int k = 0; k < 64; k++) {
        const ulonglong2* ap = (const ulonglong2*)(&sA[k * SA_STRIDE + te * 8]);
        ulonglong2 a01 = ap[0], a23 = ap[1];
        const ulonglong2* wp = (const ulonglong2*)(&sWd[k * SWD_STRIDE + to * 4]);
        ulonglong2 w01 = wp[0], w23 = wp[1];
        ull av[4] = {a01.x, a01.y, a23.x, a23.y};
        ull wv[4] = {w01.x, w01.y, w23.x, w23.y};
#pragma unroll
        for (int p = 0; p < 4; p++)
#pragma unroll
            for (int j = 0; j < 4; j++) fma_x2(acc[p][j], av[p], wv[j]);
    }

    // epilogue: relu + write + run-length masked aggregation over sorted cols
    float4 ragg = make_float4(0.f, 0.f, 0.f, 0.f);
    int curc = -1;
#pragma unroll
    for (int i = 0; i < 8; i++) {
        int pp = i >> 1, h = i & 1;
        long p = eb + te * 8 + i;
        if (p < E) {
            int r  = __ldg(&g_prow[p]);
            int c  = __ldg(&g_pcol[p]);
            float m = __ldg(&g_pmask[p]);
            float4 u = *(const float4*)(&g_ya[(size_t)r * 64 + to * 4]);
            float4 v = *(const float4*)(&g_yb[(size_t)c * 64 + to * 4]);
            float g0 = h ? unpack_hi(acc[pp][0]) : unpack_lo(acc[pp][0]);
            float g1 = h ? unpack_hi(acc[pp][1]) : unpack_lo(acc[pp][1]);
            float g2 = h ? unpack_hi(acc[pp][2]) : unpack_lo(acc[pp][2]);
            float g3 = h ? unpack_hi(acc[pp][3]) : unpack_lo(acc[pp][3]);
            float4 o;
            o.x = fmaxf(g0 + u.x + v.x, 0.f);
            o.y = fmaxf(g1 + u.y + v.y, 0.f);
            o.z = fmaxf(g2 + u.z + v.z, 0.f);
            o.w = fmaxf(g3 + u.w + v.w, 0.f);
            long dst = (DST == 0) ? p : (long)__ldg(&g_peid[p]);
            *(float4*)(&ea_out[(size_t)dst * 64 + to * 4]) = o;
            if (c != curc) {
                if (curc >= 0)
                    atomicAdd((float4*)(&agg_out[(size_t)curc * 64 + to * 4]), ragg);
                ragg = make_float4(0.f, 0.f, 0.f, 0.f);
                curc = c;
            }
            ragg.x += m * o.x; ragg.y += m * o.y;
            ragg.z += m * o.z; ragg.w += m * o.w;
        }
    }
    if (curc >= 0)
        atomicAdd((float4*)(&agg_out[(size_t)curc * 64 + to * 4]), ragg);
}

// ---------------- final node_rep + pooling ----------------
__global__ void k_final(const float* __restrict__ agg, const int* __restrict__ batch,
                        float* __restrict__ out_node, int N) {
    long idx = (long)blockIdx.x * 256 + threadIdx.x;
    if (idx >= (long)N * 64) return;
    int n = (int)(idx >> 6), d = (int)(idx & 63);
    float v = agg[idx] / (g_cntf[n] + 1.0f);
    out_node[idx] = v;
    unsigned key = __float_as_uint(v);
    key = (key & 0x80000000u) ? ~key : (key | 0x80000000u);
    atomicMax(&g_pool[(size_t)batch[n] * 64 + d], key);
}

__global__ void k_graph(const float* __restrict__ node_rep, float* __restrict__ out_graph, int B) {
    int idx = blockIdx.x * 256 + threadIdx.x;
    if (idx >= B * 192) return;
    int b = idx / 192, j = idx % 192;
    float v;
    if (j < 64) {
        unsigned k = g_pool[(size_t)b * 64 + j];
        k = (k & 0x80000000u) ? (k & 0x7FFFFFFFu) : ~k;
        v = __uint_as_float(k);
    } else if (j < 128) {
        v = node_rep[(size_t)g_head[b] * 64 + (j - 64)];
    } else {
        v = node_rep[((size_t)g_head[b] + 1) * 64 + (j - 128)];
    }
    out_graph[idx] = v;
}

// ---------------- launch ----------------
extern "C" void kernel_launch(void* const* d_in, const int* in_sizes, int n_in,
                              void* d_out, int out_size) {
    const float* x     = (const float*)d_in[0];
    const int*   eidx  = (const int*)  d_in[1];
    const int*   erel  = (const int*)  d_in[2];
    const int*   batch = (const int*)  d_in[3];
    const float* mask  = (const float*)d_in[4];
    const float* emb   = (const float*)d_in[5];
    const float* Wl[3] = {(const float*)d_in[6], (const float*)d_in[8], (const float*)d_in[10]};
    const float* bl[3] = {(const float*)d_in[7], (const float*)d_in[9], (const float*)d_in[11]};

    int N = in_sizes[0] / 6;
    int E = in_sizes[2];
    int B = (int)(((long)out_size - 64L * (N + E)) / 192L);

    const int* row = eidx;
    const int* col = eidx + E;

    float* out       = (float*)d_out;
    float* out_graph = out;
    float* out_node  = out + (size_t)B * 192;
    float* out_ea    = out_node + (size_t)N * 64;

    void *p_ea1, *p_ea2, *p_aggA, *p_aggB, *p_deg, *p_cntf, *p_gcnt, *p_pool;
    cudaGetSymbolAddress(&p_ea1,  g_ea1);
    cudaGetSymbolAddress(&p_ea2,  g_ea2);
    cudaGetSymbolAddress(&p_aggA, g_aggA);
    cudaGetSymbolAddress(&p_aggB, g_aggB);
    cudaGetSymbolAddress(&p_deg,  g_deg);
    cudaGetSymbolAddress(&p_cntf, g_cntf);
    cudaGetSymbolAddress(&p_gcnt, g_gcnt);
    cudaGetSymbolAddress(&p_pool, g_pool);
    float* ea1  = (float*)p_ea1;
    float* ea2  = (float*)p_ea2;
    float* aggA = (float*)p_aggA;
    float* aggB = (float*)p_aggB;

    cudaFuncSetAttribute(k_edge<0,0>, cudaFuncAttributeMaxDynamicSharedMemorySize, EDGE_SMEM);
    cudaFuncSetAttribute(k_edge<1,0>, cudaFuncAttributeMaxDynamicSharedMemorySize, EDGE_SMEM);
    cudaFuncSetAttribute(k_edge<1,1>, cudaFuncAttributeMaxDynamicSharedMemorySize, EDGE_SMEM);

    int grid_g = (N * 32 + 255) / 256;
    int grid_n = (N + NPB - 1) / NPB;
    int grid_e = (E + EPB - 1) / EPB;
    int M = (E > N ? E : N);

    // setup
    cudaMemsetAsync(p_deg,  0, (size_t)N * sizeof(int));
    cudaMemsetAsync(p_cntf, 0, (size_t)N * sizeof(float));
    cudaMemsetAsync(p_gcnt, 0, (size_t)B * sizeof(int));
    cudaMemsetAsync(p_pool, 0, (size_t)B * 64 * sizeof(unsigned));
    cudaMemsetAsync(p_aggB, 0, (size_t)N * 64 * sizeof(float));
    k_count<<<(M + 255) / 256, 256>>>(col, mask, batch, E, N);
    k_scan<<<1, 1024>>>(N, B);
    k_x0set<<<(B * 16 + 255) / 256, 256>>>(x, B, N);
    k_fill<<<(E + 255) / 256, 256>>>(row, col, erel, mask, E);

    // layer 0
    k_gather0<<<grid_g, 256>>>(emb, aggA, N);
    k_node<<<grid_n, 256>>>(aggA, Wl[0], bl[0], N);
    k_edge<0,0><<<grid_e, 256, EDGE_SMEM>>>(nullptr, Wl[0], emb, ea1, aggB, E);
    // layer 1
    k_node<<<grid_n, 256>>>(aggB, Wl[1], bl[1], N);
    cudaMemsetAsync(p_aggA, 0, (size_t)N * 64 * sizeof(float));
    k_edge<1,0><<<grid_e, 256, EDGE_SMEM>>>(ea1, Wl[1], nullptr, ea2, aggA, E);
    // layer 2: final ea to d_out in original edge order, agg fused
    k_node<<<grid_n, 256>>>(aggA, Wl[2], bl[2], N);
    cudaMemsetAsync(p_aggB, 0, (size_t)N * 64 * sizeof(float));
    k_edge<1,1><<<grid_e, 256, EDGE_SMEM>>>(ea2, Wl[2], nullptr, out_ea, aggB, E);
    // final node_rep + pooling + graph emb
    k_final<<<(int)(((long)N * 64 + 255) / 256), 256>>>(aggB, batch, out_node, N);
    k_graph<<<(B * 192 + 255) / 256, 256>>>(out_node, out_graph, B);
}